// round 6
// baseline (speedup 1.0000x reference)
#include <cuda_runtime.h>
#include <math.h>

// Problem constants (fixed by the reference: N, M, D, Q = 4096, 4096, 4, 4)
#define NROWS 4096
#define MCOLS 4096
#define QMIX  4
#define DDIM  4
#define NFIELD 13   // per (row,q): [0..3]=xs/y, [4..11]=pair trig, [12]=A

// Scratch feature arrays (field-major: [q][field][row]) — 832KB each.
__device__ float g_xfeat[QMIX * NFIELD * NROWS];
__device__ float g_yfeat[QMIX * NFIELD * MCOLS];

// ---------------- packed f32x2 helpers (sm_100a native dual-fp32 path) ------
typedef unsigned long long u64t;

__device__ __forceinline__ u64t fma2(u64t a, u64t b, u64t c) {
    u64t d; asm("fma.rn.f32x2 %0, %1, %2, %3;" : "=l"(d) : "l"(a), "l"(b), "l"(c));
    return d;
}
__device__ __forceinline__ u64t mul2(u64t a, u64t b) {
    u64t d; asm("mul.rn.f32x2 %0, %1, %2;" : "=l"(d) : "l"(a), "l"(b));
    return d;
}
__device__ __forceinline__ u64t add2(u64t a, u64t b) {
    u64t d; asm("add.rn.f32x2 %0, %1, %2;" : "=l"(d) : "l"(a), "l"(b));
    return d;
}
// broadcast one float into both halves of a packed f32x2 (ALU, not smem)
__device__ __forceinline__ u64t bcast2(float s) {
    u64t d; asm("mov.b64 %0, {%1,%1};" : "=l"(d) : "f"(s));
    return d;
}
// exp2 on both halves (MUFU is scalar-only; movs are register renames)
__device__ __forceinline__ u64t ex2_2(u64t v) {
    float lo, hi;
    asm("mov.b64 {%0,%1}, %2;" : "=f"(lo), "=f"(hi) : "l"(v));
    asm("ex2.approx.f32 %0, %0;" : "+f"(lo));
    asm("ex2.approx.f32 %0, %0;" : "+f"(hi));
    u64t d; asm("mov.b64 %0, {%1,%2};" : "=l"(d) : "f"(lo), "f"(hi));
    return d;
}
// load 2 packed f32x2 (4 consecutive floats, one conflict-free LDS.128)
__device__ __forceinline__ void ld2p(u64t* dst, const float* p) {
    ulonglong2 a = *reinterpret_cast<const ulonglong2*>(p);
    dst[0] = a.x; dst[1] = a.y;
}
// load 4 floats and broadcast-pack each into a f32x2 — X side (1 LDS.128)
__device__ __forceinline__ void ld4b(u64t* dst, const float* p) {
    float4 v = *reinterpret_cast<const float4*>(p);
    dst[0] = bcast2(v.x); dst[1] = bcast2(v.y);
    dst[2] = bcast2(v.z); dst[3] = bcast2(v.w);
}

// ---------------------------------------------------------------------------
// Kernel 1: per-row feature precompute (off the hot path).
//   theta_d = 2*pi*mu_qd*r_d.  Pair angles u1=th0+th1, u2=th0-th1,
//   v1=th2+th3, v2=th2-th3.  prod_d cos(th_d(x)-th_d(y)) =
//   1/4 [cos(u1x-u1y)+cos(u2x-u2y)][cos(v1x-v1y)+cos(v2x-v2y)]
//   (1/4 folded into x-side trig).  Exp part:
//   exp2(Ax + Ay + sum_d xs_d*y_d),  xs_d = 4pi^2*log2e*v_qd*x_d,
//   Ax = log2(w_q) - 2pi^2*log2e*sum v x^2,  Ay analogous.
// ---------------------------------------------------------------------------
__global__ void feat_kernel(const float* __restrict__ x, const float* __restrict__ y,
                            const float* __restrict__ lw, const float* __restrict__ mu,
                            const float* __restrict__ lv) {
    int i = blockIdx.x * blockDim.x + threadIdx.x;
    if (i >= NROWS + MCOLS) return;
    const bool isX = (i < NROWS);
    const int n = isX ? i : i - NROWS;
    const float* row = isX ? (x + n * DDIM) : (y + n * DDIM);
    float* out = isX ? g_xfeat : g_yfeat;
    const int L = isX ? NROWS : MCOLS;

    const float TWO_PI = 6.283185307179586f;
    const float C2     = 19.739208802178716f;   // 2*pi^2
    const float LOG2E  = 1.4426950408889634f;

    float r[DDIM];
#pragma unroll
    for (int d = 0; d < DDIM; ++d) r[d] = row[d];

#pragma unroll
    for (int q = 0; q < QMIX; ++q) {
        float th[DDIM];
        float sum = 0.f;
#pragma unroll
        for (int d = 0; d < DDIM; ++d) {
            float v = expf(lv[q * DDIM + d]);
            float m = mu[q * DDIM + d];
            th[d] = TWO_PI * m * r[d];
            out[(q * NFIELD + d) * L + n] = isX ? (2.f * C2 * LOG2E * v * r[d]) : r[d];
            sum += v * r[d] * r[d];
        }
        const float sc = isX ? 0.5f : 1.0f;
        float u1 = th[0] + th[1], u2 = th[0] - th[1];
        float v1 = th[2] + th[3], v2 = th[2] - th[3];
        float s, c;
        sincosf(u1, &s, &c);
        out[(q * NFIELD + 4) * L + n] = sc * c;  out[(q * NFIELD + 5) * L + n] = sc * s;
        sincosf(u2, &s, &c);
        out[(q * NFIELD + 6) * L + n] = sc * c;  out[(q * NFIELD + 7) * L + n] = sc * s;
        sincosf(v1, &s, &c);
        out[(q * NFIELD + 8) * L + n] = sc * c;  out[(q * NFIELD + 9) * L + n] = sc * s;
        sincosf(v2, &s, &c);
        out[(q * NFIELD + 10) * L + n] = sc * c; out[(q * NFIELD + 11) * L + n] = sc * s;

        float A = -C2 * LOG2E * sum;
        if (isX) A += lw[q] * LOG2E;
        out[(q * NFIELD + 12) * L + n] = A;
    }
}

// ---------------------------------------------------------------------------
// Kernel 2: 64x64 tile, 128 threads, 4x8 micro-tile per thread.
// q-body processed in two column-halves (2 packed f32x2 each) to shrink the
// live set to ~96 regs -> 5 CTAs/SM.  Y fields stored chunk-permuted in smem
// (even 16B chunks then odd) so each half's Y load is one conflict-free
// LDS.128 at base + h*128B + tx*16B.
// ---------------------------------------------------------------------------
__global__ void __launch_bounds__(128, 5)
sm_tile_kernel(float* __restrict__ out) {
    __shared__ float XS[QMIX * NFIELD * 64];   // 13312 B
    __shared__ float YS[QMIX * NFIELD * 64];   // 13312 B (chunk-permuted)

    const int rowBase = blockIdx.y * 64;
    const int colBase = blockIdx.x * 64;
    const int tid = threadIdx.x;

    // Cooperative smem fill: 52 segments x 16 float4 per side.
    // Y chunks permuted: chunk j -> (j&1) ? 8+(j>>1) : (j>>1).
    {
        float4* xs4 = reinterpret_cast<float4*>(XS);
        float4* ys4 = reinterpret_cast<float4*>(YS);
        for (int s = tid; s < QMIX * NFIELD * 16; s += 128) {
            const int seg = s >> 4;
            const int j   = s & 15;
            xs4[s] = *reinterpret_cast<const float4*>(&g_xfeat[seg * NROWS + rowBase + j * 4]);
            const int jp = (j & 1) ? (8 + (j >> 1)) : (j >> 1);
            ys4[seg * 16 + jp] = *reinterpret_cast<const float4*>(&g_yfeat[seg * MCOLS + colBase + j * 4]);
        }
    }
    __syncthreads();

    const int tx = tid & 7;        // 8 column groups (8 cols = 4 packed)
    const int ty = tid >> 3;       // 16 row groups (4 rows)
    const int r0 = ty * 4;
    const int yo = tx * 4;         // float offset of this thread's 16B Y chunk

    u64t acc[16];                  // [r][cpacked]; half h covers cpacked h*2..h*2+1
#pragma unroll
    for (int i = 0; i < 16; ++i) acc[i] = 0ull;

#pragma unroll 1
    for (int q = 0; q < QMIX; ++q) {
        const float* Xq = XS + q * NFIELD * 64;
        const float* Yq = YS + q * NFIELD * 64;

#pragma unroll
        for (int h = 0; h < 2; ++h) {
            const int ho = h * 32 + yo;    // permuted: half h chunk for this tx

            u64t ev[8];    // exp argument -> exp value -> exp*t1
            u64t p[8];     // t1, then t2

            // ---- exp argument: Ax + Ay + sum_d xs_d*y_d ----
            {
                u64t xa[4], yb[2];
                ld4b(xa, Xq + 12 * 64 + r0);
                ld2p(yb, Yq + 12 * 64 + ho);
#pragma unroll
                for (int r = 0; r < 4; ++r)
#pragma unroll
                    for (int c = 0; c < 2; ++c) ev[r * 2 + c] = add2(xa[r], yb[c]);
#pragma unroll
                for (int d = 0; d < 4; ++d) {
                    ld4b(xa, Xq + d * 64 + r0);
                    ld2p(yb, Yq + d * 64 + ho);
#pragma unroll
                    for (int r = 0; r < 4; ++r)
#pragma unroll
                        for (int c = 0; c < 2; ++c)
                            ev[r * 2 + c] = fma2(xa[r], yb[c], ev[r * 2 + c]);
                }
            }
#pragma unroll
            for (int i = 0; i < 8; ++i) ev[i] = ex2_2(ev[i]);

            // ---- t1 = 0.5*[cos(u1x-u1y)+cos(u2x-u2y)] ----
            {
                u64t xa[4], yb[2];
                ld4b(xa, Xq + 4 * 64 + r0);
                ld2p(yb, Yq + 4 * 64 + ho);
#pragma unroll
                for (int r = 0; r < 4; ++r)
#pragma unroll
                    for (int c = 0; c < 2; ++c) p[r * 2 + c] = mul2(xa[r], yb[c]);
#pragma unroll
                for (int f = 5; f <= 7; ++f) {
                    ld4b(xa, Xq + f * 64 + r0);
                    ld2p(yb, Yq + f * 64 + ho);
#pragma unroll
                    for (int r = 0; r < 4; ++r)
#pragma unroll
                        for (int c = 0; c < 2; ++c)
                            p[r * 2 + c] = fma2(xa[r], yb[c], p[r * 2 + c]);
                }
            }
#pragma unroll
            for (int i = 0; i < 8; ++i) ev[i] = mul2(ev[i], p[i]);

            // ---- t2 = 0.5*[cos(v1x-v1y)+cos(v2x-v2y)], accumulate ----
            {
                u64t xa[4], yb[2];
                ld4b(xa, Xq + 8 * 64 + r0);
                ld2p(yb, Yq + 8 * 64 + ho);
#pragma unroll
                for (int r = 0; r < 4; ++r)
#pragma unroll
                    for (int c = 0; c < 2; ++c) p[r * 2 + c] = mul2(xa[r], yb[c]);
#pragma unroll
                for (int f = 9; f <= 11; ++f) {
                    ld4b(xa, Xq + f * 64 + r0);
                    ld2p(yb, Yq + f * 64 + ho);
#pragma unroll
                    for (int r = 0; r < 4; ++r)
#pragma unroll
                        for (int c = 0; c < 2; ++c)
                            p[r * 2 + c] = fma2(xa[r], yb[c], p[r * 2 + c]);
                }
            }
#pragma unroll
            for (int r = 0; r < 4; ++r)
#pragma unroll
                for (int c = 0; c < 2; ++c)
                    acc[r * 4 + h * 2 + c] =
                        fma2(ev[r * 2 + c], p[r * 2 + c], acc[r * 4 + h * 2 + c]);
        }
    }

    // Store 4x8 micro-tile: each packed row = 8 floats = 2x 16B stores.
#pragma unroll
    for (int r = 0; r < 4; ++r) {
        const size_t base = (size_t)(rowBase + r0 + r) * MCOLS + colBase + tx * 8;
        ulonglong2 v0, v1;
        v0.x = acc[r * 4 + 0]; v0.y = acc[r * 4 + 1];
        v1.x = acc[r * 4 + 2]; v1.y = acc[r * 4 + 3];
        *reinterpret_cast<ulonglong2*>(&out[base])     = v0;
        *reinterpret_cast<ulonglong2*>(&out[base + 4]) = v1;
    }
}

extern "C" void kernel_launch(void* const* d_in, const int* in_sizes, int n_in,
                              void* d_out, int out_size) {
    const float* x  = (const float*)d_in[0];
    const float* y  = (const float*)d_in[1];
    const float* lw = (const float*)d_in[2];
    const float* mu = (const float*)d_in[3];
    const float* lv = (const float*)d_in[4];
    float* out = (float*)d_out;

    (void)in_sizes; (void)n_in; (void)out_size;

    feat_kernel<<<(NROWS + MCOLS + 255) / 256, 256>>>(x, y, lw, mu, lv);

    dim3 grid(MCOLS / 64, NROWS / 64);
    sm_tile_kernel<<<grid, 128>>>(out);
}

// round 7
// speedup vs baseline: 1.0515x; 1.0515x over previous
#include <cuda_runtime.h>
#include <math.h>

// Problem constants (fixed by the reference: N, M, D, Q = 4096, 4096, 4, 4)
#define NROWS 4096
#define MCOLS 4096
#define QMIX  4
#define DDIM  4
#define NFIELD 13   // per (row,q): [0..3]=xs/y, [4..11]=pair trig, [12]=A

// Scratch feature arrays (field-major: [q][field][row]) — 832KB each.
__device__ float g_xfeat[QMIX * NFIELD * NROWS];
__device__ float g_yfeat[QMIX * NFIELD * MCOLS];

// ---------------- packed f32x2 helpers (sm_100a native dual-fp32 path) ------
typedef unsigned long long u64t;

__device__ __forceinline__ u64t fma2(u64t a, u64t b, u64t c) {
    u64t d; asm("fma.rn.f32x2 %0, %1, %2, %3;" : "=l"(d) : "l"(a), "l"(b), "l"(c));
    return d;
}
__device__ __forceinline__ u64t mul2(u64t a, u64t b) {
    u64t d; asm("mul.rn.f32x2 %0, %1, %2;" : "=l"(d) : "l"(a), "l"(b));
    return d;
}
__device__ __forceinline__ u64t add2(u64t a, u64t b) {
    u64t d; asm("add.rn.f32x2 %0, %1, %2;" : "=l"(d) : "l"(a), "l"(b));
    return d;
}
// broadcast one float into both halves of a packed f32x2 (ALU, not smem)
__device__ __forceinline__ u64t bcast2(float s) {
    u64t d; asm("mov.b64 %0, {%1,%1};" : "=l"(d) : "f"(s));
    return d;
}
// exp2 on both halves (MUFU is scalar-only; movs are register renames)
__device__ __forceinline__ u64t ex2_2(u64t v) {
    float lo, hi;
    asm("mov.b64 {%0,%1}, %2;" : "=f"(lo), "=f"(hi) : "l"(v));
    asm("ex2.approx.f32 %0, %0;" : "+f"(lo));
    asm("ex2.approx.f32 %0, %0;" : "+f"(hi));
    u64t d; asm("mov.b64 %0, {%1,%2};" : "=l"(d) : "f"(lo), "f"(hi));
    return d;
}
// Y side: load 4 packed f32x2 for this thread's 8 columns from a
// chunk-permuted field (two conflict-free LDS.128, 128B apart).
__device__ __forceinline__ void ld4y(u64t* dst, const float* p) {
    ulonglong2 a = *reinterpret_cast<const ulonglong2*>(p);        // cols 0-3
    ulonglong2 b = *reinterpret_cast<const ulonglong2*>(p + 32);   // cols 4-7
    dst[0] = a.x; dst[1] = a.y; dst[2] = b.x; dst[3] = b.y;
}
// X side: load 2 floats (LDS.64) and broadcast-pack each
__device__ __forceinline__ void ld2b(u64t* dst, const float* p) {
    float2 v = *reinterpret_cast<const float2*>(p);
    dst[0] = bcast2(v.x); dst[1] = bcast2(v.y);
}

// ---------------------------------------------------------------------------
// Kernel 1: per-row feature precompute (off the hot path).
//   theta_d = 2*pi*mu_qd*r_d.  Pair angles u1=th0+th1, u2=th0-th1,
//   v1=th2+th3, v2=th2-th3.  prod_d cos(th_d(x)-th_d(y)) =
//   1/4 [cos(u1x-u1y)+cos(u2x-u2y)][cos(v1x-v1y)+cos(v2x-v2y)]
//   (1/4 folded into x-side trig).  Exp part:
//   exp2(Ax + Ay + sum_d xs_d*y_d),  xs_d = 4pi^2*log2e*v_qd*x_d,
//   Ax = log2(w_q) - 2pi^2*log2e*sum v x^2,  Ay analogous.
// ---------------------------------------------------------------------------
__global__ void feat_kernel(const float* __restrict__ x, const float* __restrict__ y,
                            const float* __restrict__ lw, const float* __restrict__ mu,
                            const float* __restrict__ lv) {
    int i = blockIdx.x * blockDim.x + threadIdx.x;
    if (i >= NROWS + MCOLS) return;
    const bool isX = (i < NROWS);
    const int n = isX ? i : i - NROWS;
    const float* row = isX ? (x + n * DDIM) : (y + n * DDIM);
    float* out = isX ? g_xfeat : g_yfeat;
    const int L = isX ? NROWS : MCOLS;

    const float TWO_PI = 6.283185307179586f;
    const float C2     = 19.739208802178716f;   // 2*pi^2
    const float LOG2E  = 1.4426950408889634f;

    float r[DDIM];
#pragma unroll
    for (int d = 0; d < DDIM; ++d) r[d] = row[d];

#pragma unroll
    for (int q = 0; q < QMIX; ++q) {
        float th[DDIM];
        float sum = 0.f;
#pragma unroll
        for (int d = 0; d < DDIM; ++d) {
            float v = expf(lv[q * DDIM + d]);
            float m = mu[q * DDIM + d];
            th[d] = TWO_PI * m * r[d];
            out[(q * NFIELD + d) * L + n] = isX ? (2.f * C2 * LOG2E * v * r[d]) : r[d];
            sum += v * r[d] * r[d];
        }
        const float sc = isX ? 0.5f : 1.0f;
        float u1 = th[0] + th[1], u2 = th[0] - th[1];
        float v1 = th[2] + th[3], v2 = th[2] - th[3];
        float s, c;
        sincosf(u1, &s, &c);
        out[(q * NFIELD + 4) * L + n] = sc * c;  out[(q * NFIELD + 5) * L + n] = sc * s;
        sincosf(u2, &s, &c);
        out[(q * NFIELD + 6) * L + n] = sc * c;  out[(q * NFIELD + 7) * L + n] = sc * s;
        sincosf(v1, &s, &c);
        out[(q * NFIELD + 8) * L + n] = sc * c;  out[(q * NFIELD + 9) * L + n] = sc * s;
        sincosf(v2, &s, &c);
        out[(q * NFIELD + 10) * L + n] = sc * c; out[(q * NFIELD + 11) * L + n] = sc * s;

        float A = -C2 * LOG2E * sum;
        if (isX) A += lw[q] * LOG2E;
        out[(q * NFIELD + 12) * L + n] = A;
    }
}

// ---------------------------------------------------------------------------
// Kernel 2: 32x64 tile, 128 threads, 2x8 micro-tile per thread (2 rows x
// 4 packed f32x2).  Small live set -> 6 CTAs/SM (24 warps).  Y fields
// chunk-permuted in smem so both LDS.128 per field are conflict-free;
// X loaded as LDS.64 + register broadcast packs.
// ---------------------------------------------------------------------------
__global__ void __launch_bounds__(128, 6)
sm_tile_kernel(float* __restrict__ out) {
    __shared__ float XS[QMIX * NFIELD * 32];   // 6656 B
    __shared__ float YS[QMIX * NFIELD * 64];   // 13312 B (chunk-permuted)

    const int rowBase = blockIdx.y * 32;
    const int colBase = blockIdx.x * 64;
    const int tid = threadIdx.x;

    // Cooperative smem fill.
    {
        float4* xs4 = reinterpret_cast<float4*>(XS);
        for (int s = tid; s < QMIX * NFIELD * 8; s += 128) {
            const int seg = s >> 3;
            const int j   = s & 7;
            xs4[s] = *reinterpret_cast<const float4*>(&g_xfeat[seg * NROWS + rowBase + j * 4]);
        }
        // Y chunks permuted: chunk j -> (j&1) ? 8+(j>>1) : (j>>1)
        float4* ys4 = reinterpret_cast<float4*>(YS);
        for (int s = tid; s < QMIX * NFIELD * 16; s += 128) {
            const int seg = s >> 4;
            const int j   = s & 15;
            const int jp = (j & 1) ? (8 + (j >> 1)) : (j >> 1);
            ys4[seg * 16 + jp] = *reinterpret_cast<const float4*>(&g_yfeat[seg * MCOLS + colBase + j * 4]);
        }
    }
    __syncthreads();

    const int tx = tid & 7;        // 8 column groups (8 cols = 4 packed)
    const int ty = tid >> 3;       // 16 row groups (2 rows each)
    const int r0 = ty * 2;
    const int yo = tx * 4;         // float offset of this thread's first 16B Y chunk

    u64t acc[8];                   // [r*4 + cpacked]
#pragma unroll
    for (int i = 0; i < 8; ++i) acc[i] = 0ull;

#pragma unroll 1
    for (int q = 0; q < QMIX; ++q) {
        const float* Xq = XS + q * NFIELD * 32;
        const float* Yq = YS + q * NFIELD * 64;

        u64t ev[8];    // exp argument -> exp value -> exp*t1
        u64t p[8];     // t1, then t2

        // ---- exp argument: Ax + Ay + sum_d xs_d*y_d ----
        {
            u64t xa[2], yb[4];
            ld2b(xa, Xq + 12 * 32 + r0);
            ld4y(yb, Yq + 12 * 64 + yo);
#pragma unroll
            for (int r = 0; r < 2; ++r)
#pragma unroll
                for (int c = 0; c < 4; ++c) ev[r * 4 + c] = add2(xa[r], yb[c]);
#pragma unroll
            for (int d = 0; d < 4; ++d) {
                ld2b(xa, Xq + d * 32 + r0);
                ld4y(yb, Yq + d * 64 + yo);
#pragma unroll
                for (int r = 0; r < 2; ++r)
#pragma unroll
                    for (int c = 0; c < 4; ++c)
                        ev[r * 4 + c] = fma2(xa[r], yb[c], ev[r * 4 + c]);
            }
        }
#pragma unroll
        for (int i = 0; i < 8; ++i) ev[i] = ex2_2(ev[i]);

        // ---- t1 = 0.5*[cos(u1x-u1y)+cos(u2x-u2y)] (0.5 folded into X) ----
        {
            u64t xa[2], yb[4];
            ld2b(xa, Xq + 4 * 32 + r0);
            ld4y(yb, Yq + 4 * 64 + yo);
#pragma unroll
            for (int r = 0; r < 2; ++r)
#pragma unroll
                for (int c = 0; c < 4; ++c) p[r * 4 + c] = mul2(xa[r], yb[c]);
#pragma unroll
            for (int f = 5; f <= 7; ++f) {
                ld2b(xa, Xq + f * 32 + r0);
                ld4y(yb, Yq + f * 64 + yo);
#pragma unroll
                for (int r = 0; r < 2; ++r)
#pragma unroll
                    for (int c = 0; c < 4; ++c)
                        p[r * 4 + c] = fma2(xa[r], yb[c], p[r * 4 + c]);
            }
        }
        // fold t1 into ev (p dies, reused below)
#pragma unroll
        for (int i = 0; i < 8; ++i) ev[i] = mul2(ev[i], p[i]);

        // ---- t2 = 0.5*[cos(v1x-v1y)+cos(v2x-v2y)], accumulate ----
        {
            u64t xa[2], yb[4];
            ld2b(xa, Xq + 8 * 32 + r0);
            ld4y(yb, Yq + 8 * 64 + yo);
#pragma unroll
            for (int r = 0; r < 2; ++r)
#pragma unroll
                for (int c = 0; c < 4; ++c) p[r * 4 + c] = mul2(xa[r], yb[c]);
#pragma unroll
            for (int f = 9; f <= 11; ++f) {
                ld2b(xa, Xq + f * 32 + r0);
                ld4y(yb, Yq + f * 64 + yo);
#pragma unroll
                for (int r = 0; r < 2; ++r)
#pragma unroll
                    for (int c = 0; c < 4; ++c)
                        p[r * 4 + c] = fma2(xa[r], yb[c], p[r * 4 + c]);
            }
        }
#pragma unroll
        for (int i = 0; i < 8; ++i) acc[i] = fma2(ev[i], p[i], acc[i]);
    }

    // Store 2x8 micro-tile: each row = 8 floats = 2x 16B stores.
#pragma unroll
    for (int r = 0; r < 2; ++r) {
        const size_t base = (size_t)(rowBase + r0 + r) * MCOLS + colBase + tx * 8;
        ulonglong2 v0, v1;
        v0.x = acc[r * 4 + 0]; v0.y = acc[r * 4 + 1];
        v1.x = acc[r * 4 + 2]; v1.y = acc[r * 4 + 3];
        *reinterpret_cast<ulonglong2*>(&out[base])     = v0;
        *reinterpret_cast<ulonglong2*>(&out[base + 4]) = v1;
    }
}

extern "C" void kernel_launch(void* const* d_in, const int* in_sizes, int n_in,
                              void* d_out, int out_size) {
    const float* x  = (const float*)d_in[0];
    const float* y  = (const float*)d_in[1];
    const float* lw = (const float*)d_in[2];
    const float* mu = (const float*)d_in[3];
    const float* lv = (const float*)d_in[4];
    float* out = (float*)d_out;

    (void)in_sizes; (void)n_in; (void)out_size;

    feat_kernel<<<(NROWS + MCOLS + 255) / 256, 256>>>(x, y, lw, mu, lv);

    dim3 grid(MCOLS / 64, NROWS / 32);
    sm_tile_kernel<<<grid, 128>>>(out);
}

// round 8
// speedup vs baseline: 1.5020x; 1.4283x over previous
#include <cuda_runtime.h>
#include <math.h>

// Problem constants (fixed by the reference: N, M, D, Q = 4096, 4096, 4, 4)
#define NROWS 4096
#define MCOLS 4096
#define QMIX  4
#define DDIM  4
#define NFIELD 13   // per (row,q): [0..3]=xs/y, [4..11]=pair trig, [12]=A

// Scratch feature arrays (field-major: [q][field][row]) — 832KB each.
__device__ float g_xfeat[QMIX * NFIELD * NROWS];
__device__ float g_yfeat[QMIX * NFIELD * MCOLS];

// ---------------- packed f32x2 helpers (sm_100a native dual-fp32 path) ------
typedef unsigned long long u64t;

__device__ __forceinline__ u64t fma2(u64t a, u64t b, u64t c) {
    u64t d; asm("fma.rn.f32x2 %0, %1, %2, %3;" : "=l"(d) : "l"(a), "l"(b), "l"(c));
    return d;
}
__device__ __forceinline__ u64t mul2(u64t a, u64t b) {
    u64t d; asm("mul.rn.f32x2 %0, %1, %2;" : "=l"(d) : "l"(a), "l"(b));
    return d;
}
__device__ __forceinline__ u64t add2(u64t a, u64t b) {
    u64t d; asm("add.rn.f32x2 %0, %1, %2;" : "=l"(d) : "l"(a), "l"(b));
    return d;
}
// broadcast one float into both halves of a packed f32x2 (ALU, not smem)
__device__ __forceinline__ u64t bcast2(float s) {
    u64t d; asm("mov.b64 %0, {%1,%1};" : "=l"(d) : "f"(s));
    return d;
}
// exp2 on both halves (MUFU is scalar-only; movs are register renames)
__device__ __forceinline__ u64t ex2_2(u64t v) {
    float lo, hi;
    asm("mov.b64 {%0,%1}, %2;" : "=f"(lo), "=f"(hi) : "l"(v));
    asm("ex2.approx.f32 %0, %0;" : "+f"(lo));
    asm("ex2.approx.f32 %0, %0;" : "+f"(hi));
    u64t d; asm("mov.b64 %0, {%1,%2};" : "=l"(d) : "f"(lo), "f"(hi));
    return d;
}
// Y side: 4 packed f32x2 (8 cols) from a chunk-permuted field:
// two conflict-free LDS.128 at +0 and +128B.
__device__ __forceinline__ void ld4y(u64t* dst, const float* p) {
    ulonglong2 a = *reinterpret_cast<const ulonglong2*>(p);        // cols 0-3
    ulonglong2 b = *reinterpret_cast<const ulonglong2*>(p + 32);   // cols 4-7
    dst[0] = a.x; dst[1] = a.y; dst[2] = b.x; dst[3] = b.y;
}
// X side: load 4 floats (1 conflict-free LDS.128) and broadcast-pack each
__device__ __forceinline__ void ld4b(u64t* dst, const float* p) {
    float4 v = *reinterpret_cast<const float4*>(p);
    dst[0] = bcast2(v.x); dst[1] = bcast2(v.y);
    dst[2] = bcast2(v.z); dst[3] = bcast2(v.w);
}

// ---------------------------------------------------------------------------
// Kernel 1: per-row feature precompute (off the hot path).
//   theta_d = 2*pi*mu_qd*r_d.  Pair angles u1=th0+th1, u2=th0-th1,
//   v1=th2+th3, v2=th2-th3.  prod_d cos(th_d(x)-th_d(y)) =
//   1/4 [cos(u1x-u1y)+cos(u2x-u2y)][cos(v1x-v1y)+cos(v2x-v2y)]
//   (1/4 folded into x-side trig).  Exp part:
//   exp2(Ax + Ay + sum_d xs_d*y_d),  xs_d = 4pi^2*log2e*v_qd*x_d,
//   Ax = log2(w_q) - 2pi^2*log2e*sum v x^2,  Ay analogous.
// ---------------------------------------------------------------------------
__global__ void feat_kernel(const float* __restrict__ x, const float* __restrict__ y,
                            const float* __restrict__ lw, const float* __restrict__ mu,
                            const float* __restrict__ lv) {
    int i = blockIdx.x * blockDim.x + threadIdx.x;
    if (i >= NROWS + MCOLS) return;
    const bool isX = (i < NROWS);
    const int n = isX ? i : i - NROWS;
    const float* row = isX ? (x + n * DDIM) : (y + n * DDIM);
    float* out = isX ? g_xfeat : g_yfeat;
    const int L = isX ? NROWS : MCOLS;

    const float TWO_PI = 6.283185307179586f;
    const float C2     = 19.739208802178716f;   // 2*pi^2
    const float LOG2E  = 1.4426950408889634f;

    float r[DDIM];
#pragma unroll
    for (int d = 0; d < DDIM; ++d) r[d] = row[d];

#pragma unroll
    for (int q = 0; q < QMIX; ++q) {
        float th[DDIM];
        float sum = 0.f;
#pragma unroll
        for (int d = 0; d < DDIM; ++d) {
            float v = expf(lv[q * DDIM + d]);
            float m = mu[q * DDIM + d];
            th[d] = TWO_PI * m * r[d];
            out[(q * NFIELD + d) * L + n] = isX ? (2.f * C2 * LOG2E * v * r[d]) : r[d];
            sum += v * r[d] * r[d];
        }
        const float sc = isX ? 0.5f : 1.0f;
        float u1 = th[0] + th[1], u2 = th[0] - th[1];
        float v1 = th[2] + th[3], v2 = th[2] - th[3];
        float s, c;
        sincosf(u1, &s, &c);
        out[(q * NFIELD + 4) * L + n] = sc * c;  out[(q * NFIELD + 5) * L + n] = sc * s;
        sincosf(u2, &s, &c);
        out[(q * NFIELD + 6) * L + n] = sc * c;  out[(q * NFIELD + 7) * L + n] = sc * s;
        sincosf(v1, &s, &c);
        out[(q * NFIELD + 8) * L + n] = sc * c;  out[(q * NFIELD + 9) * L + n] = sc * s;
        sincosf(v2, &s, &c);
        out[(q * NFIELD + 10) * L + n] = sc * c; out[(q * NFIELD + 11) * L + n] = sc * s;

        float A = -C2 * LOG2E * sum;
        if (isX) A += lw[q] * LOG2E;
        out[(q * NFIELD + 12) * L + n] = A;
    }
}

// ---------------------------------------------------------------------------
// Kernel 2: 64x64 tile, 128 threads, 4x8 micro-tile per thread (4 rows x
// 4 packed f32x2).  Y fields chunk-permuted in smem (even 16B chunks first)
// so both Y LDS.128 per field are conflict-free; X via 1 LDS.128 + register
// broadcast packs.  ex2 interleaved with the independent t1 stage.
// ---------------------------------------------------------------------------
__global__ void __launch_bounds__(128, 4)
sm_tile_kernel(float* __restrict__ out) {
    __shared__ float XS[QMIX * NFIELD * 64];   // 13312 B
    __shared__ float YS[QMIX * NFIELD * 64];   // 13312 B (chunk-permuted)

    const int rowBase = blockIdx.y * 64;
    const int colBase = blockIdx.x * 64;
    const int tid = threadIdx.x;

    // Cooperative smem fill: 52 segments x 16 float4 per side.
    // Y chunks permuted: chunk j -> (j&1) ? 8+(j>>1) : (j>>1).
    {
        float4* xs4 = reinterpret_cast<float4*>(XS);
        float4* ys4 = reinterpret_cast<float4*>(YS);
        for (int s = tid; s < QMIX * NFIELD * 16; s += 128) {
            const int seg = s >> 4;
            const int j   = s & 15;
            xs4[s] = *reinterpret_cast<const float4*>(&g_xfeat[seg * NROWS + rowBase + j * 4]);
            const int jp = (j & 1) ? (8 + (j >> 1)) : (j >> 1);
            ys4[seg * 16 + jp] = *reinterpret_cast<const float4*>(&g_yfeat[seg * MCOLS + colBase + j * 4]);
        }
    }
    __syncthreads();

    const int tx = tid & 7;        // 8 column groups (8 cols = 4 packed)
    const int ty = tid >> 3;       // 16 row groups (4 rows)
    const int r0 = ty * 4;
    const int yo = tx * 4;         // float offset of this thread's even 16B chunk

    u64t acc[16];
#pragma unroll
    for (int i = 0; i < 16; ++i) acc[i] = 0ull;

#pragma unroll 1
    for (int q = 0; q < QMIX; ++q) {
        const float* Xq = XS + q * NFIELD * 64;
        const float* Yq = YS + q * NFIELD * 64;

        u64t ev[16];   // exp argument -> exp value -> exp*t1
        u64t p[16];    // t1, then t2

        // ---- exp argument: Ax + Ay + sum_d xs_d*y_d ----
        {
            u64t xa[4], yb[4];
            ld4b(xa, Xq + 12 * 64 + r0);
            ld4y(yb, Yq + 12 * 64 + yo);
#pragma unroll
            for (int r = 0; r < 4; ++r)
#pragma unroll
                for (int c = 0; c < 4; ++c) ev[r * 4 + c] = add2(xa[r], yb[c]);
#pragma unroll
            for (int d = 0; d < 4; ++d) {
                ld4b(xa, Xq + d * 64 + r0);
                ld4y(yb, Yq + d * 64 + yo);
#pragma unroll
                for (int r = 0; r < 4; ++r)
#pragma unroll
                    for (int c = 0; c < 4; ++c)
                        ev[r * 4 + c] = fma2(xa[r], yb[c], ev[r * 4 + c]);
            }
        }

        // ---- t1 stage with ex2 interleaved (independent streams) ----
        {
            u64t xa[4], yb[4];
            ld4b(xa, Xq + 4 * 64 + r0);
            ld4y(yb, Yq + 4 * 64 + yo);
            // kick off 4 ex2 while the first t1 field is in flight
#pragma unroll
            for (int i = 0; i < 4; ++i) ev[i] = ex2_2(ev[i]);
#pragma unroll
            for (int r = 0; r < 4; ++r)
#pragma unroll
                for (int c = 0; c < 4; ++c) p[r * 4 + c] = mul2(xa[r], yb[c]);
#pragma unroll
            for (int f = 5; f <= 7; ++f) {
                ld4b(xa, Xq + f * 64 + r0);
                ld4y(yb, Yq + f * 64 + yo);
                // 4 more ex2 per field iteration (12 remaining over 3 fields)
#pragma unroll
                for (int i = 0; i < 4; ++i)
                    ev[(f - 4) * 4 + i] = ex2_2(ev[(f - 4) * 4 + i]);
#pragma unroll
                for (int r = 0; r < 4; ++r)
#pragma unroll
                    for (int c = 0; c < 4; ++c)
                        p[r * 4 + c] = fma2(xa[r], yb[c], p[r * 4 + c]);
            }
        }
        // fold t1 into ev (p dies, reused below)
#pragma unroll
        for (int i = 0; i < 16; ++i) ev[i] = mul2(ev[i], p[i]);

        // ---- t2 = 0.5*[cos(v1x-v1y)+cos(v2x-v2y)], accumulate ----
        {
            u64t xa[4], yb[4];
            ld4b(xa, Xq + 8 * 64 + r0);
            ld4y(yb, Yq + 8 * 64 + yo);
#pragma unroll
            for (int r = 0; r < 4; ++r)
#pragma unroll
                for (int c = 0; c < 4; ++c) p[r * 4 + c] = mul2(xa[r], yb[c]);
#pragma unroll
            for (int f = 9; f <= 11; ++f) {
                ld4b(xa, Xq + f * 64 + r0);
                ld4y(yb, Yq + f * 64 + yo);
#pragma unroll
                for (int r = 0; r < 4; ++r)
#pragma unroll
                    for (int c = 0; c < 4; ++c)
                        p[r * 4 + c] = fma2(xa[r], yb[c], p[r * 4 + c]);
            }
        }
#pragma unroll
        for (int i = 0; i < 16; ++i) acc[i] = fma2(ev[i], p[i], acc[i]);
    }

    // Store 4x8 micro-tile: each packed row = 8 floats = 2x 16B stores.
#pragma unroll
    for (int r = 0; r < 4; ++r) {
        const size_t base = (size_t)(rowBase + r0 + r) * MCOLS + colBase + tx * 8;
        ulonglong2 v0, v1;
        v0.x = acc[r * 4 + 0]; v0.y = acc[r * 4 + 1];
        v1.x = acc[r * 4 + 2]; v1.y = acc[r * 4 + 3];
        *reinterpret_cast<ulonglong2*>(&out[base])     = v0;
        *reinterpret_cast<ulonglong2*>(&out[base + 4]) = v1;
    }
}

extern "C" void kernel_launch(void* const* d_in, const int* in_sizes, int n_in,
                              void* d_out, int out_size) {
    const float* x  = (const float*)d_in[0];
    const float* y  = (const float*)d_in[1];
    const float* lw = (const float*)d_in[2];
    const float* mu = (const float*)d_in[3];
    const float* lv = (const float*)d_in[4];
    float* out = (float*)d_out;

    (void)in_sizes; (void)n_in; (void)out_size;

    feat_kernel<<<(NROWS + MCOLS + 255) / 256, 256>>>(x, y, lw, mu, lv);

    dim3 grid(MCOLS / 64, NROWS / 64);
    sm_tile_kernel<<<grid, 128>>>(out);
}